// round 7
// baseline (speedup 1.0000x reference)
#include <cuda_runtime.h>
#include <cuda_bf16.h>

// SSIM loss: X,Y (32,8,320,320) fp32, 7x7 uniform box (valid), out = 1 - mean(S)
//
// Vertical-first separable box sums. This round:
//  - TILE_H=32 (2 segs x 16 rows, IN=22): vertical redundancy 1.75 -> 1.375
//  - interior-block specialization (no predication on 75% of blocks)
//  - phase-2 chunks of 15 cols: 1.4 LDS.128/output (was 1.75)
//  - smem 33.3KB, __launch_bounds__(128,6)

#define WIN      7
#define IMG      320
#define OUT      314
#define NIMG     256
#define NELEM    25240576.0

#define COLS     64
#define TILE_W   58
#define TILE_H   32
#define SEG_ROWS 16
#define SSTRIDE  (COLS + 1)          // 65 float4 entries per row
#define GRID_X   6
#define GRID_Y   10
#define NBLOCKS  (GRID_X * GRID_Y * NIMG)   // 15360

__device__ double g_accum;
__device__ unsigned int g_count;

// ---- packed f32x2 helpers (sm_103a) ----
__device__ __forceinline__ float2 f2add(float2 a, float2 b) {
    unsigned long long ra = *(unsigned long long*)&a;
    unsigned long long rb = *(unsigned long long*)&b;
    unsigned long long rd;
    asm("add.rn.f32x2 %0, %1, %2;" : "=l"(rd) : "l"(ra), "l"(rb));
    return *(float2*)&rd;
}
__device__ __forceinline__ float2 f2mul(float2 a, float2 b) {
    unsigned long long ra = *(unsigned long long*)&a;
    unsigned long long rb = *(unsigned long long*)&b;
    unsigned long long rd;
    asm("mul.rn.f32x2 %0, %1, %2;" : "=l"(rd) : "l"(ra), "l"(rb));
    return *(float2*)&rd;
}
__device__ __forceinline__ float2 f2fma(float2 a, float2 b, float2 c) {
    unsigned long long ra = *(unsigned long long*)&a;
    unsigned long long rb = *(unsigned long long*)&b;
    unsigned long long rc = *(unsigned long long*)&c;
    unsigned long long rd;
    asm("fma.rn.f32x2 %0, %1, %2, %3;" : "=l"(rd) : "l"(ra), "l"(rb), "l"(rc));
    return *(float2*)&rd;
}

template <bool INTERIOR>
__device__ __forceinline__ float ssim_tile(
    const float* __restrict__ Xb, const float* __restrict__ Yb,
    int tx0, int ty0, int tid,
    float4 (&s_E)[TILE_H][SSTRIDE],
    float iw, float C1s, float C2s, float epsS)
{
    const float2 neg1 = make_float2(-1.f, -1.f);

    // ---------------- Phase 1: vertical window sums (coalesced) ------------
    {
        const int col = tid & (COLS - 1);
        const int seg = tid >> 6;               // 0..1
        const int gx  = tx0 + col;
        const int gy0 = ty0 + seg * SEG_ROWS;
        const float* xp = Xb + (size_t)gy0 * IMG + gx;
        const float* yp = Yb + (size_t)gy0 * IMG + gx;
        const bool colok = INTERIOR || (gx < IMG);

        // first half: input rows 0..13 -> outputs 0..7
        float xa[14], ya[14];
        #pragma unroll
        for (int j = 0; j < 14; j++) {
            const bool ok = INTERIOR || (colok && (gy0 + j < IMG));
            xa[j] = ok ? __ldg(xp + (size_t)j * IMG) : 0.0f;
            ya[j] = ok ? __ldg(yp + (size_t)j * IMG) : 0.0f;
        }

        float2 P = make_float2(0.f, 0.f);
        float2 Q = make_float2(0.f, 0.f);
        float  R = 0.f;
        #pragma unroll
        for (int k = 0; k < WIN; k++) {
            const float2 p = make_float2(xa[k], ya[k]);
            P = f2add(P, p);
            Q = f2fma(p, p, Q);
            R = fmaf(xa[k], ya[k], R);
        }
        const int rbase = seg * SEG_ROWS;
        s_E[rbase][col] = make_float4(P.x, P.y, Q.x + Q.y, R);

        #pragma unroll
        for (int r = 1; r < 8; r++) {
            const float2 pn = make_float2(xa[r + 6], ya[r + 6]);
            const float2 po = make_float2(xa[r - 1], ya[r - 1]);
            P = f2add(P, pn);
            P = f2fma(po, neg1, P);
            Q = f2fma(pn, pn, Q);
            const float2 mpo = f2mul(po, neg1);
            Q = f2fma(mpo, po, Q);
            R = fmaf(pn.x, pn.y, R);
            R = fmaf(-po.x, po.y, R);
            s_E[rbase + r][col] = make_float4(P.x, P.y, Q.x + Q.y, R);
        }

        // second half: input rows 14..21 -> outputs 8..15
        float xb[8], yb[8];
        #pragma unroll
        for (int j = 0; j < 8; j++) {
            const bool ok = INTERIOR || (colok && (gy0 + 14 + j < IMG));
            xb[j] = ok ? __ldg(xp + (size_t)(14 + j) * IMG) : 0.0f;
            yb[j] = ok ? __ldg(yp + (size_t)(14 + j) * IMG) : 0.0f;
        }

        #pragma unroll
        for (int r = 8; r < SEG_ROWS; r++) {
            const float2 pn = make_float2(xb[r - 8], yb[r - 8]);
            const float2 po = (r < 15) ? make_float2(xa[r - 1], ya[r - 1])
                                       : make_float2(xb[0], yb[0]);
            P = f2add(P, pn);
            P = f2fma(po, neg1, P);
            Q = f2fma(pn, pn, Q);
            const float2 mpo = f2mul(po, neg1);
            Q = f2fma(mpo, po, Q);
            R = fmaf(pn.x, pn.y, R);
            R = fmaf(-po.x, po.y, R);
            s_E[rbase + r][col] = make_float4(P.x, P.y, Q.x + Q.y, R);
        }
    }
    __syncthreads();

    // ---------------- Phase 2: horizontal sliding + SSIM -------------------
    const float COV  = 49.0f / 48.0f;
    const float COV2 = 2.0f * COV;

    float local = 0.f;
    {
        const int r  = tid & (TILE_H - 1);      // 0..31 output row
        const int q  = tid >> 5;                // 0..3 column chunk
        const int c0 = q * 15;
        const int cmax = (q == 3) ? 13 : 15;    // 45+13=58 total cols
        const bool rowok = INTERIOR || (ty0 + r < OUT);

        float4 ring[7];
        float2 Sp = make_float2(0.f, 0.f);
        float2 Sq = make_float2(0.f, 0.f);
        #pragma unroll
        for (int k = 0; k < WIN; k++) {
            const float4 e = s_E[r][c0 + k];
            ring[k] = e;
            Sp = f2add(Sp, make_float2(e.x, e.y));
            Sq = f2add(Sq, make_float2(e.z, e.w));
        }

        #pragma unroll
        for (int ci = 0; ci < 15; ci++) {
            const int c = c0 + ci;
            const bool active = (ci < cmax) &&
                (INTERIOR || (rowok && (tx0 + c < OUT)));

            const float sx = Sp.x, sy = Sp.y;
            const float sqq = Sq.x, sxy = Sq.y;
            const float2 PP = f2mul(Sp, Sp);
            const float t1 = sx * sy;
            const float b1 = PP.x + PP.y;
            const float A1 = fmaf(t1, 2.0f, C1s);
            const float B1 = b1 + C1s;
            const float A2 = fmaf(COV2, fmaf(iw, sxy, -t1), C2s);
            const float B2 = fmaf(COV,  fmaf(iw, sqq, -b1), C2s);
            const float num = A1 * A2;
            const float den = fmaf(B1, B2, epsS);
            if (active) local += __fdividef(num, den);

            if (ci + 1 < cmax) {
                const float4 ne = s_E[r][c + 7];
                const float4 oe = ring[ci % 7];
                Sp = f2add(Sp, make_float2(ne.x, ne.y));
                Sp = f2fma(make_float2(oe.x, oe.y), neg1, Sp);
                Sq = f2add(Sq, make_float2(ne.z, ne.w));
                Sq = f2fma(make_float2(oe.z, oe.w), neg1, Sq);
                ring[ci % 7] = ne;
            }
        }
    }
    return local;
}

__global__ __launch_bounds__(128, 6) void ssim_main_kernel(
    const float* __restrict__ X, const float* __restrict__ Y,
    const float* __restrict__ data_range, const float* __restrict__ w,
    float* __restrict__ out)
{
    __shared__ float4 s_E[TILE_H][SSTRIDE];
    __shared__ float  warpsum[4];

    const int img = blockIdx.z;
    const int tx0 = blockIdx.x * TILE_W;
    const int ty0 = blockIdx.y * TILE_H;
    const float* Xb = X + (size_t)img * IMG * IMG;
    const float* Yb = Y + (size_t)img * IMG * IMG;
    const int tid = threadIdx.x;

    const float w0  = w[0];
    const float iw  = 1.0f / w0;                // ~49
    const float dr  = data_range[0];
    const float c1t = 0.01f * dr;
    const float c2t = 0.03f * dr;
    const float C1s = (c1t * c1t) * iw * iw;
    const float C2s = (c2t * c2t) * iw * iw;
    const float epsS = 1e-8f * (iw * iw) * (iw * iw);

    float local;
    if (blockIdx.x < 5 && blockIdx.y < 9) {
        local = ssim_tile<true >(Xb, Yb, tx0, ty0, tid, s_E, iw, C1s, C2s, epsS);
    } else {
        local = ssim_tile<false>(Xb, Yb, tx0, ty0, tid, s_E, iw, C1s, C2s, epsS);
    }

    // ---------------- Block reduction + fused finalize ----------------------
    #pragma unroll
    for (int off = 16; off > 0; off >>= 1)
        local += __shfl_down_sync(0xffffffffu, local, off);
    if ((tid & 31) == 0) warpsum[tid >> 5] = local;
    __syncthreads();
    if (tid == 0) {
        const float v = warpsum[0] + warpsum[1] + warpsum[2] + warpsum[3];
        atomicAdd(&g_accum, (double)v);
        __threadfence();
        const unsigned done = atomicAdd(&g_count, 1u);
        if (done == NBLOCKS - 1) {
            const double total = atomicAdd(&g_accum, 0.0);
            out[0] = (float)(1.0 - total / NELEM);
            g_accum = 0.0;            // reset for next graph replay
            g_count = 0u;
        }
    }
}

extern "C" void kernel_launch(void* const* d_in, const int* in_sizes, int n_in,
                              void* d_out, int out_size) {
    const float* X  = (const float*)d_in[0];
    const float* Y  = (const float*)d_in[1];
    const float* dr = (const float*)d_in[2];
    const float* w  = (const float*)d_in[3];
    float* out = (float*)d_out;

    dim3 grid(GRID_X, GRID_Y, NIMG);
    ssim_main_kernel<<<grid, 128>>>(X, Y, dr, w, out);
}

// round 8
// speedup vs baseline: 1.1159x; 1.1159x over previous
#include <cuda_runtime.h>
#include <cuda_bf16.h>

// SSIM loss: X,Y (32,8,320,320) fp32, 7x7 uniform box (valid), out = 1 - mean(S)
//
// R6 structure (best: 82.4us): TILE_H=16, 2 segs x 8 rows, float4 SMEM plane
// (sx, sy, sxx+syy, sxy), chunk-of-8 phase 2, launch_bounds(128,8).
// This round adds ONLY interior-block specialization (79% of blocks skip all
// boundary predication) — kept register-neutral.

#define WIN      7
#define IMG      320
#define OUT      314
#define NIMG     256
#define NELEM    25240576.0

#define COLS     64
#define TILE_W   58
#define TILE_H   16
#define SEG_ROWS 8
#define IN_ROWS  14
#define SSTRIDE  (COLS + 1)          // 65 float4 entries per row
#define GRID_X   6
#define GRID_Y   20
#define NBLOCKS  (GRID_X * GRID_Y * NIMG)   // 30720

__device__ double g_accum;
__device__ unsigned int g_count;

// ---- packed f32x2 helpers (sm_103a) ----
__device__ __forceinline__ float2 f2add(float2 a, float2 b) {
    unsigned long long ra = *(unsigned long long*)&a;
    unsigned long long rb = *(unsigned long long*)&b;
    unsigned long long rd;
    asm("add.rn.f32x2 %0, %1, %2;" : "=l"(rd) : "l"(ra), "l"(rb));
    return *(float2*)&rd;
}
__device__ __forceinline__ float2 f2mul(float2 a, float2 b) {
    unsigned long long ra = *(unsigned long long*)&a;
    unsigned long long rb = *(unsigned long long*)&b;
    unsigned long long rd;
    asm("mul.rn.f32x2 %0, %1, %2;" : "=l"(rd) : "l"(ra), "l"(rb));
    return *(float2*)&rd;
}
__device__ __forceinline__ float2 f2fma(float2 a, float2 b, float2 c) {
    unsigned long long ra = *(unsigned long long*)&a;
    unsigned long long rb = *(unsigned long long*)&b;
    unsigned long long rc = *(unsigned long long*)&c;
    unsigned long long rd;
    asm("fma.rn.f32x2 %0, %1, %2, %3;" : "=l"(rd) : "l"(ra), "l"(rb), "l"(rc));
    return *(float2*)&rd;
}

template <bool INTERIOR>
__device__ __forceinline__ float ssim_tile(
    const float* __restrict__ Xb, const float* __restrict__ Yb,
    int tx0, int ty0, int tid,
    float4 (&s_E)[TILE_H][SSTRIDE],
    float iw, float C1s, float C2s, float epsS)
{
    const float2 neg1 = make_float2(-1.f, -1.f);

    // ---------------- Phase 1: vertical window sums (coalesced) ------------
    {
        const int col = tid & (COLS - 1);       // lane-contiguous columns
        const int seg = tid >> 6;               // 0..1, 8 output rows each
        const int gx  = tx0 + col;
        const int gy0 = ty0 + seg * SEG_ROWS;
        const bool colok = INTERIOR || (gx < IMG);
        const float* xp = Xb + (size_t)gy0 * IMG + gx;
        const float* yp = Yb + (size_t)gy0 * IMG + gx;

        float xv[IN_ROWS], yv[IN_ROWS];
        #pragma unroll
        for (int j = 0; j < IN_ROWS; j++) {
            const bool ok = INTERIOR || (colok && (gy0 + j < IMG));
            xv[j] = ok ? __ldg(xp + (size_t)j * IMG) : 0.0f;
            yv[j] = ok ? __ldg(yp + (size_t)j * IMG) : 0.0f;
        }

        float2 P = make_float2(0.f, 0.f);       // (sx, sy)
        float2 Q = make_float2(0.f, 0.f);       // (sxx, syy) -> summed at store
        float  R = 0.f;                         // sxy
        #pragma unroll
        for (int k = 0; k < WIN; k++) {
            const float2 p = make_float2(xv[k], yv[k]);
            P = f2add(P, p);
            Q = f2fma(p, p, Q);
            R = fmaf(xv[k], yv[k], R);
        }
        const int rbase = seg * SEG_ROWS;
        s_E[rbase][col] = make_float4(P.x, P.y, Q.x + Q.y, R);

        #pragma unroll
        for (int r = 1; r < SEG_ROWS; r++) {
            const float2 pn = make_float2(xv[r + 6], yv[r + 6]);
            const float2 po = make_float2(xv[r - 1], yv[r - 1]);
            P = f2add(P, pn);
            P = f2fma(po, neg1, P);
            Q = f2fma(pn, pn, Q);
            const float2 mpo = f2mul(po, neg1);
            Q = f2fma(mpo, po, Q);
            R = fmaf(pn.x, pn.y, R);
            R = fmaf(-po.x, po.y, R);
            s_E[rbase + r][col] = make_float4(P.x, P.y, Q.x + Q.y, R);
        }
    }
    __syncthreads();

    // ---------------- Phase 2: horizontal sliding + SSIM -------------------
    const float COV  = 49.0f / 48.0f;
    const float COV2 = 2.0f * COV;

    float local = 0.f;
    {
        const int r  = tid & (TILE_H - 1);      // output row in tile
        const int q  = tid >> 4;                // 0..7 column chunk
        const int c0 = q * 8;
        const bool rowok = INTERIOR || (ty0 + r < OUT);

        float4 ring[7];
        float2 Sp = make_float2(0.f, 0.f);      // (sx, sy)
        float2 Sq = make_float2(0.f, 0.f);      // (sqq, sxy)
        #pragma unroll
        for (int k = 0; k < WIN; k++) {
            const float4 e = s_E[r][c0 + k];
            ring[k] = e;
            Sp = f2add(Sp, make_float2(e.x, e.y));
            Sq = f2add(Sq, make_float2(e.z, e.w));
        }

        #pragma unroll
        for (int ci = 0; ci < 8; ci++) {
            const int c = c0 + ci;
            const bool active = (c < TILE_W) &&
                (INTERIOR || (rowok && (tx0 + c < OUT)));

            const float sx = Sp.x, sy = Sp.y;
            const float sqq = Sq.x, sxy = Sq.y;
            const float2 PP = f2mul(Sp, Sp);          // (sx^2, sy^2)
            const float t1 = sx * sy;
            const float b1 = PP.x + PP.y;
            const float A1 = fmaf(t1, 2.0f, C1s);
            const float B1 = b1 + C1s;
            const float A2 = fmaf(COV2, fmaf(iw, sxy, -t1), C2s);
            const float B2 = fmaf(COV,  fmaf(iw, sqq, -b1), C2s);
            const float num = A1 * A2;
            const float den = fmaf(B1, B2, epsS);
            if (active) local += __fdividef(num, den);

            if (ci < 7 && c + 7 < COLS) {
                const float4 ne = s_E[r][c + 7];
                const float4 oe = ring[ci];
                Sp = f2add(Sp, make_float2(ne.x, ne.y));
                Sp = f2fma(make_float2(oe.x, oe.y), neg1, Sp);
                Sq = f2add(Sq, make_float2(ne.z, ne.w));
                Sq = f2fma(make_float2(oe.z, oe.w), neg1, Sq);
            }
        }
    }
    return local;
}

__global__ __launch_bounds__(128, 8) void ssim_main_kernel(
    const float* __restrict__ X, const float* __restrict__ Y,
    const float* __restrict__ data_range, const float* __restrict__ w,
    float* __restrict__ out)
{
    __shared__ float4 s_E[TILE_H][SSTRIDE];
    __shared__ float  warpsum[4];

    const int img = blockIdx.z;
    const int tx0 = blockIdx.x * TILE_W;
    const int ty0 = blockIdx.y * TILE_H;
    const float* Xb = X + (size_t)img * IMG * IMG;
    const float* Yb = Y + (size_t)img * IMG * IMG;
    const int tid = threadIdx.x;

    const float w0  = w[0];
    const float iw  = 1.0f / w0;                // ~49
    const float dr  = data_range[0];
    const float c1t = 0.01f * dr;
    const float c2t = 0.03f * dr;
    const float C1s = (c1t * c1t) * iw * iw;
    const float C2s = (c2t * c2t) * iw * iw;
    const float epsS = 1e-8f * (iw * iw) * (iw * iw);

    float local;
    if (blockIdx.x < GRID_X - 1 && blockIdx.y < GRID_Y - 1) {
        local = ssim_tile<true >(Xb, Yb, tx0, ty0, tid, s_E, iw, C1s, C2s, epsS);
    } else {
        local = ssim_tile<false>(Xb, Yb, tx0, ty0, tid, s_E, iw, C1s, C2s, epsS);
    }

    // ---------------- Block reduction + fused finalize ----------------------
    #pragma unroll
    for (int off = 16; off > 0; off >>= 1)
        local += __shfl_down_sync(0xffffffffu, local, off);
    if ((tid & 31) == 0) warpsum[tid >> 5] = local;
    __syncthreads();
    if (tid == 0) {
        const float v = warpsum[0] + warpsum[1] + warpsum[2] + warpsum[3];
        atomicAdd(&g_accum, (double)v);
        __threadfence();
        const unsigned done = atomicAdd(&g_count, 1u);
        if (done == NBLOCKS - 1) {
            const double total = atomicAdd(&g_accum, 0.0);
            out[0] = (float)(1.0 - total / NELEM);
            g_accum = 0.0;            // reset for next graph replay
            g_count = 0u;
        }
    }
}

extern "C" void kernel_launch(void* const* d_in, const int* in_sizes, int n_in,
                              void* d_out, int out_size) {
    const float* X  = (const float*)d_in[0];
    const float* Y  = (const float*)d_in[1];
    const float* dr = (const float*)d_in[2];
    const float* w  = (const float*)d_in[3];
    float* out = (float*)d_out;

    dim3 grid(GRID_X, GRID_Y, NIMG);
    ssim_main_kernel<<<grid, 128>>>(X, Y, dr, w, out);
}

// round 9
// speedup vs baseline: 1.2225x; 1.0956x over previous
#include <cuda_runtime.h>
#include <cuda_bf16.h>

// SSIM loss: X,Y (32,8,320,320) fp32, 7x7 uniform box (valid), out = 1 - mean(S)
//
// R6 structure (best: 82.4us) with boundary handling by ADDRESS CLAMPING:
//  - single code body (no template duplication -> fits I$)
//  - clamped loads are safe: duplicated elements only feed windows whose
//    output index >= OUT, which the `active` predicate discards.
//  - rows 0..7 provably in-bounds (gy0 <= 312) -> immediate-offset LDGs;
//    only rows 8..13 use min(gy0+j, 319) offsets.

#define WIN      7
#define IMG      320
#define OUT      314
#define NIMG     256
#define NELEM    25240576.0

#define COLS     64
#define TILE_W   58
#define TILE_H   16
#define SEG_ROWS 8
#define IN_ROWS  14
#define SSTRIDE  (COLS + 1)          // 65 float4 entries per row
#define GRID_X   6
#define GRID_Y   20
#define NBLOCKS  (GRID_X * GRID_Y * NIMG)   // 30720

__device__ double g_accum;
__device__ unsigned int g_count;

// ---- packed f32x2 helpers (sm_103a) ----
__device__ __forceinline__ float2 f2add(float2 a, float2 b) {
    unsigned long long ra = *(unsigned long long*)&a;
    unsigned long long rb = *(unsigned long long*)&b;
    unsigned long long rd;
    asm("add.rn.f32x2 %0, %1, %2;" : "=l"(rd) : "l"(ra), "l"(rb));
    return *(float2*)&rd;
}
__device__ __forceinline__ float2 f2mul(float2 a, float2 b) {
    unsigned long long ra = *(unsigned long long*)&a;
    unsigned long long rb = *(unsigned long long*)&b;
    unsigned long long rd;
    asm("mul.rn.f32x2 %0, %1, %2;" : "=l"(rd) : "l"(ra), "l"(rb));
    return *(float2*)&rd;
}
__device__ __forceinline__ float2 f2fma(float2 a, float2 b, float2 c) {
    unsigned long long ra = *(unsigned long long*)&a;
    unsigned long long rb = *(unsigned long long*)&b;
    unsigned long long rc = *(unsigned long long*)&c;
    unsigned long long rd;
    asm("fma.rn.f32x2 %0, %1, %2, %3;" : "=l"(rd) : "l"(ra), "l"(rb), "l"(rc));
    return *(float2*)&rd;
}

__global__ __launch_bounds__(128, 8) void ssim_main_kernel(
    const float* __restrict__ X, const float* __restrict__ Y,
    const float* __restrict__ data_range, const float* __restrict__ w,
    float* __restrict__ out)
{
    __shared__ float4 s_E[TILE_H][SSTRIDE];   // (sx, sy, sxx+syy, sxy)
    __shared__ float  warpsum[4];

    const int img = blockIdx.z;
    const int tx0 = blockIdx.x * TILE_W;
    const int ty0 = blockIdx.y * TILE_H;
    const float* Xb = X + (size_t)img * IMG * IMG;
    const float* Yb = Y + (size_t)img * IMG * IMG;
    const int tid = threadIdx.x;
    const float2 neg1 = make_float2(-1.f, -1.f);

    // ---------------- Phase 1: vertical window sums (coalesced) ------------
    {
        const int col = tid & (COLS - 1);           // lane-contiguous columns
        const int seg = tid >> 6;                   // 0..1, 8 output rows each
        const int gx  = min(tx0 + col, IMG - 1);    // column clamp (safe: see hdr)
        const int gy0 = ty0 + seg * SEG_ROWS;       // <= 312 always
        const float* xp = Xb + (size_t)gy0 * IMG + gx;
        const float* yp = Yb + (size_t)gy0 * IMG + gx;

        float xv[IN_ROWS], yv[IN_ROWS];
        // rows 0..7: provably in-bounds (gy0+7 <= 319) -> immediate offsets
        #pragma unroll
        for (int j = 0; j < 8; j++) {
            xv[j] = __ldg(xp + j * IMG);
            yv[j] = __ldg(yp + j * IMG);
        }
        // rows 8..13: clamp row index (duplicates only feed discarded outputs)
        #pragma unroll
        for (int j = 8; j < IN_ROWS; j++) {
            const int dj = min(gy0 + j, IMG - 1) - gy0;
            xv[j] = __ldg(xp + dj * IMG);
            yv[j] = __ldg(yp + dj * IMG);
        }

        float2 P = make_float2(0.f, 0.f);       // (sx, sy)
        float2 Q = make_float2(0.f, 0.f);       // (sxx, syy) -> summed at store
        float  R = 0.f;                         // sxy
        #pragma unroll
        for (int k = 0; k < WIN; k++) {
            const float2 p = make_float2(xv[k], yv[k]);
            P = f2add(P, p);
            Q = f2fma(p, p, Q);
            R = fmaf(xv[k], yv[k], R);
        }
        const int rbase = seg * SEG_ROWS;
        s_E[rbase][col] = make_float4(P.x, P.y, Q.x + Q.y, R);

        #pragma unroll
        for (int r = 1; r < SEG_ROWS; r++) {
            const float2 pn = make_float2(xv[r + 6], yv[r + 6]);
            const float2 po = make_float2(xv[r - 1], yv[r - 1]);
            P = f2add(P, pn);
            P = f2fma(po, neg1, P);
            Q = f2fma(pn, pn, Q);
            const float2 mpo = f2mul(po, neg1);
            Q = f2fma(mpo, po, Q);
            R = fmaf(pn.x, pn.y, R);
            R = fmaf(-po.x, po.y, R);
            s_E[rbase + r][col] = make_float4(P.x, P.y, Q.x + Q.y, R);
        }
    }
    __syncthreads();

    // ---------------- Phase 2: horizontal sliding + SSIM -------------------
    // Rescaled algebra (everything * (1/w)^2): no per-pixel wscale mults.
    const float w0  = w[0];
    const float iw  = 1.0f / w0;                // ~49
    const float dr  = data_range[0];
    const float c1t = 0.01f * dr;
    const float c2t = 0.03f * dr;
    const float C1s = (c1t * c1t) * iw * iw;
    const float C2s = (c2t * c2t) * iw * iw;
    const float COV  = 49.0f / 48.0f;
    const float COV2 = 2.0f * COV;
    const float epsS = 1e-8f * (iw * iw) * (iw * iw);

    float local = 0.f;
    {
        const int r  = tid & (TILE_H - 1);      // output row in tile
        const int q  = tid >> 4;                // 0..7 column chunk
        const int c0 = q * 8;
        const bool rowok = (ty0 + r < OUT);

        float4 ring[7];
        float2 Sp = make_float2(0.f, 0.f);      // (sx, sy)
        float2 Sq = make_float2(0.f, 0.f);      // (sqq, sxy)
        #pragma unroll
        for (int k = 0; k < WIN; k++) {
            const float4 e = s_E[r][c0 + k];
            ring[k] = e;
            Sp = f2add(Sp, make_float2(e.x, e.y));
            Sq = f2add(Sq, make_float2(e.z, e.w));
        }

        #pragma unroll
        for (int ci = 0; ci < 8; ci++) {
            const int c = c0 + ci;
            const bool active = rowok && (c < TILE_W) && (tx0 + c < OUT);

            const float sx = Sp.x, sy = Sp.y;
            const float sqq = Sq.x, sxy = Sq.y;
            const float2 PP = f2mul(Sp, Sp);          // (sx^2, sy^2)
            const float t1 = sx * sy;
            const float b1 = PP.x + PP.y;
            const float A1 = fmaf(t1, 2.0f, C1s);
            const float B1 = b1 + C1s;
            const float A2 = fmaf(COV2, fmaf(iw, sxy, -t1), C2s);
            const float B2 = fmaf(COV,  fmaf(iw, sqq, -b1), C2s);
            const float num = A1 * A2;
            const float den = fmaf(B1, B2, epsS);
            if (active) local += __fdividef(num, den);

            if (ci < 7 && c + 7 < COLS) {
                const float4 ne = s_E[r][c + 7];
                const float4 oe = ring[ci];
                Sp = f2add(Sp, make_float2(ne.x, ne.y));
                Sp = f2fma(make_float2(oe.x, oe.y), neg1, Sp);
                Sq = f2add(Sq, make_float2(ne.z, ne.w));
                Sq = f2fma(make_float2(oe.z, oe.w), neg1, Sq);
            }
        }
    }

    // ---------------- Block reduction + fused finalize ----------------------
    #pragma unroll
    for (int off = 16; off > 0; off >>= 1)
        local += __shfl_down_sync(0xffffffffu, local, off);
    if ((tid & 31) == 0) warpsum[tid >> 5] = local;
    __syncthreads();
    if (tid == 0) {
        const float v = warpsum[0] + warpsum[1] + warpsum[2] + warpsum[3];
        atomicAdd(&g_accum, (double)v);
        __threadfence();
        const unsigned done = atomicAdd(&g_count, 1u);
        if (done == NBLOCKS - 1) {
            const double total = atomicAdd(&g_accum, 0.0);
            out[0] = (float)(1.0 - total / NELEM);
            g_accum = 0.0;            // reset for next graph replay
            g_count = 0u;
        }
    }
}

extern "C" void kernel_launch(void* const* d_in, const int* in_sizes, int n_in,
                              void* d_out, int out_size) {
    const float* X  = (const float*)d_in[0];
    const float* Y  = (const float*)d_in[1];
    const float* dr = (const float*)d_in[2];
    const float* w  = (const float*)d_in[3];
    float* out = (float*)d_out;

    dim3 grid(GRID_X, GRID_Y, NIMG);
    ssim_main_kernel<<<grid, 128>>>(X, Y, dr, w, out);
}

// round 10
// speedup vs baseline: 1.2516x; 1.0238x over previous
#include <cuda_runtime.h>
#include <cuda_bf16.h>

// SSIM loss: X,Y (32,8,320,320) fp32, 7x7 uniform box (valid), out = 1 - mean(S)
//
// Strip-mined persistent vertical slide:
//  - each block: 64 input cols x 80-output-row strip, 5 iterations of 16 rows
//  - 6-row vertical halo carried in registers across iterations
//    (16 LDG per 16 E-rows vs 28 previously; redundancy 1.75 -> 1.15)
//  - phase 2 per iteration identical to the proven R6 chunk-of-8 design
//  - smem 16.7KB, launch_bounds(128,8), iteration loop NOT unrolled (I$)

#define WIN      7
#define IMG      320
#define OUT      314
#define NIMG     256
#define NELEM    25240576.0

#define COLS     64
#define TILE_W   58
#define STRIP    80                  // output rows per block strip
#define HALF     40                  // rows per thread-segment
#define NITER    5                   // iterations of 16 buffer rows (8 per seg)
#define SSTRIDE  (COLS + 1)          // 65 float4 entries per row
#define GRID_X   6
#define GRID_Y   4
#define NBLOCKS  (GRID_X * GRID_Y * NIMG)   // 6144

__device__ double g_accum;
__device__ unsigned int g_count;

// ---- packed f32x2 helpers (sm_103a) ----
__device__ __forceinline__ float2 f2add(float2 a, float2 b) {
    unsigned long long ra = *(unsigned long long*)&a;
    unsigned long long rb = *(unsigned long long*)&b;
    unsigned long long rd;
    asm("add.rn.f32x2 %0, %1, %2;" : "=l"(rd) : "l"(ra), "l"(rb));
    return *(float2*)&rd;
}
__device__ __forceinline__ float2 f2mul(float2 a, float2 b) {
    unsigned long long ra = *(unsigned long long*)&a;
    unsigned long long rb = *(unsigned long long*)&b;
    unsigned long long rd;
    asm("mul.rn.f32x2 %0, %1, %2;" : "=l"(rd) : "l"(ra), "l"(rb));
    return *(float2*)&rd;
}
__device__ __forceinline__ float2 f2fma(float2 a, float2 b, float2 c) {
    unsigned long long ra = *(unsigned long long*)&a;
    unsigned long long rb = *(unsigned long long*)&b;
    unsigned long long rc = *(unsigned long long*)&c;
    unsigned long long rd;
    asm("fma.rn.f32x2 %0, %1, %2, %3;" : "=l"(rd) : "l"(ra), "l"(rb), "l"(rc));
    return *(float2*)&rd;
}

__global__ __launch_bounds__(128, 8) void ssim_main_kernel(
    const float* __restrict__ X, const float* __restrict__ Y,
    const float* __restrict__ data_range, const float* __restrict__ w,
    float* __restrict__ out)
{
    __shared__ float4 s_E[16][SSTRIDE];   // (sx, sy, sxx+syy, sxy)
    __shared__ float  warpsum[4];

    const int img = blockIdx.z;
    const int tx0 = blockIdx.x * TILE_W;
    const int ty0 = blockIdx.y * STRIP;
    const float* Xb = X + (size_t)img * IMG * IMG;
    const float* Yb = Y + (size_t)img * IMG * IMG;
    const int tid = threadIdx.x;
    const float2 neg1 = make_float2(-1.f, -1.f);

    // constants for SSIM (rescaled by (1/w)^2)
    const float w0  = w[0];
    const float iw  = 1.0f / w0;                // ~49
    const float dr  = data_range[0];
    const float c1t = 0.01f * dr;
    const float c2t = 0.03f * dr;
    const float C1s = (c1t * c1t) * iw * iw;
    const float C2s = (c2t * c2t) * iw * iw;
    const float COV  = 49.0f / 48.0f;
    const float COV2 = 2.0f * COV;
    const float epsS = 1e-8f * (iw * iw) * (iw * iw);

    // phase-1 coords: thread = (column, segment)
    const int col = tid & (COLS - 1);
    const int seg = tid >> 6;                   // 0..1
    const int gx  = min(tx0 + col, IMG - 1);    // clamped cols feed only
                                                // discarded outputs
    const int base = ty0 + seg * HALF;          // first input row of segment
    const float* xp = Xb + (size_t)base * IMG + gx;
    const float* yp = Yb + (size_t)base * IMG + gx;

    // phase-2 coords
    const int r2 = tid & 15;                    // buffer row
    const int q  = tid >> 4;                    // 0..7 column chunk
    const int c0 = q * 8;

    // prime carry: input rows base..base+5 (max base=280 -> always in-bounds)
    float cx[6], cy[6];
    #pragma unroll
    for (int j = 0; j < 6; j++) {
        cx[j] = __ldg(xp + j * IMG);
        cy[j] = __ldg(yp + j * IMG);
    }
    const float* xp2 = xp + 6 * IMG;
    const float* yp2 = yp + 6 * IMG;

    float local = 0.f;

    #pragma unroll 1
    for (int it = 0; it < NITER; ++it) {
        // ---- load 8 new input rows (front-batched for MLP) ----
        float nx[8], ny[8];
        const int rbase = base + it * 8 + 6;
        if (rbase + 7 < IMG) {                  // warp-uniform branch
            #pragma unroll
            for (int j = 0; j < 8; j++) {
                nx[j] = __ldg(xp2 + j * IMG);
                ny[j] = __ldg(yp2 + j * IMG);
            }
        } else {                                // only strip 3 / seg 1 / it 4
            #pragma unroll
            for (int j = 0; j < 8; j++) {
                const int dj = min(rbase + j, IMG - 1) - rbase;
                nx[j] = __ldg(xp2 + dj * IMG);
                ny[j] = __ldg(yp2 + dj * IMG);
            }
        }
        xp2 += 8 * IMG; yp2 += 8 * IMG;

        // ---- vertical slide over 14-row window (carry[6] + new[8]) ----
        {
            float wx[14], wy[14];
            #pragma unroll
            for (int j = 0; j < 6; j++) { wx[j] = cx[j]; wy[j] = cy[j]; }
            #pragma unroll
            for (int j = 0; j < 8; j++) { wx[6 + j] = nx[j]; wy[6 + j] = ny[j]; }

            float2 P = make_float2(0.f, 0.f);
            float2 Q = make_float2(0.f, 0.f);
            float  R = 0.f;
            #pragma unroll
            for (int k = 0; k < WIN; k++) {
                const float2 p = make_float2(wx[k], wy[k]);
                P = f2add(P, p);
                Q = f2fma(p, p, Q);
                R = fmaf(wx[k], wy[k], R);
            }
            const int rb = seg * 8;
            s_E[rb][col] = make_float4(P.x, P.y, Q.x + Q.y, R);

            #pragma unroll
            for (int r = 1; r < 8; r++) {
                const float2 pn = make_float2(wx[r + 6], wy[r + 6]);
                const float2 po = make_float2(wx[r - 1], wy[r - 1]);
                P = f2add(P, pn);
                P = f2fma(po, neg1, P);
                Q = f2fma(pn, pn, Q);
                const float2 mpo = f2mul(po, neg1);
                Q = f2fma(mpo, po, Q);
                R = fmaf(pn.x, pn.y, R);
                R = fmaf(-po.x, po.y, R);
                s_E[rb + r][col] = make_float4(P.x, P.y, Q.x + Q.y, R);
            }
        }
        // carry = last 6 window rows = new[2..7]
        #pragma unroll
        for (int j = 0; j < 6; j++) { cx[j] = nx[j + 2]; cy[j] = ny[j + 2]; }

        __syncthreads();

        // ---- phase 2: horizontal sliding + SSIM on 16 buffer rows ----
        {
            const int gy = ty0 + ((r2 < 8) ? (it * 8 + r2)
                                           : (HALF + it * 8 + (r2 - 8)));
            const bool rowok = (gy < OUT);

            float4 ring[7];
            float2 Sp = make_float2(0.f, 0.f);
            float2 Sq = make_float2(0.f, 0.f);
            #pragma unroll
            for (int k = 0; k < WIN; k++) {
                const float4 e = s_E[r2][c0 + k];
                ring[k] = e;
                Sp = f2add(Sp, make_float2(e.x, e.y));
                Sq = f2add(Sq, make_float2(e.z, e.w));
            }

            #pragma unroll
            for (int ci = 0; ci < 8; ci++) {
                const int c = c0 + ci;
                const bool active = rowok && (c < TILE_W) && (tx0 + c < OUT);

                const float sx = Sp.x, sy = Sp.y;
                const float sqq = Sq.x, sxy = Sq.y;
                const float2 PP = f2mul(Sp, Sp);
                const float t1 = sx * sy;
                const float b1 = PP.x + PP.y;
                const float A1 = fmaf(t1, 2.0f, C1s);
                const float B1 = b1 + C1s;
                const float A2 = fmaf(COV2, fmaf(iw, sxy, -t1), C2s);
                const float B2 = fmaf(COV,  fmaf(iw, sqq, -b1), C2s);
                const float num = A1 * A2;
                const float den = fmaf(B1, B2, epsS);
                if (active) local += __fdividef(num, den);

                if (ci < 7 && c + 7 < COLS) {
                    const float4 ne = s_E[r2][c + 7];
                    const float4 oe = ring[ci];
                    Sp = f2add(Sp, make_float2(ne.x, ne.y));
                    Sp = f2fma(make_float2(oe.x, oe.y), neg1, Sp);
                    Sq = f2add(Sq, make_float2(ne.z, ne.w));
                    Sq = f2fma(make_float2(oe.z, oe.w), neg1, Sq);
                }
            }
        }
        __syncthreads();   // protect s_E before next iteration's writes
    }

    // ---------------- Block reduction + fused finalize ----------------------
    #pragma unroll
    for (int off = 16; off > 0; off >>= 1)
        local += __shfl_down_sync(0xffffffffu, local, off);
    if ((tid & 31) == 0) warpsum[tid >> 5] = local;
    __syncthreads();
    if (tid == 0) {
        const float v = warpsum[0] + warpsum[1] + warpsum[2] + warpsum[3];
        atomicAdd(&g_accum, (double)v);
        __threadfence();
        const unsigned done = atomicAdd(&g_count, 1u);
        if (done == NBLOCKS - 1) {
            const double total = atomicAdd(&g_accum, 0.0);
            out[0] = (float)(1.0 - total / NELEM);
            g_accum = 0.0;            // reset for next graph replay
            g_count = 0u;
        }
    }
}

extern "C" void kernel_launch(void* const* d_in, const int* in_sizes, int n_in,
                              void* d_out, int out_size) {
    const float* X  = (const float*)d_in[0];
    const float* Y  = (const float*)d_in[1];
    const float* dr = (const float*)d_in[2];
    const float* w  = (const float*)d_in[3];
    float* out = (float*)d_out;

    dim3 grid(GRID_X, GRID_Y, NIMG);
    ssim_main_kernel<<<grid, 128>>>(X, Y, dr, w, out);
}